// round 4
// baseline (speedup 1.0000x reference)
#include <cuda_runtime.h>
#include <cstdint>
#include <cstddef>

#define BATCH 256
#define TSEQ  512
#define IDIM  64
#define HDIM  512
#define ODIM  512
#define GRID_J 16            // j-CTAs per batch group (barrier group size)
#define GRID_B 8             // independent batch groups
#define STEP_THREADS 128

typedef unsigned long long ull;

// ---- scratch (static device allocations only) ----
__device__ float g_xp[(size_t)TSEQ * BATCH * HDIM];   // [t][b][h], 256 MiB
// hidden state, transposed plain float: g_ht[buf][j*BATCH + b]
__device__ float g_ht[2][(size_t)HDIM * BATCH];       // 1 MiB
// one barrier counter per batch group, padded 128B apart
__device__ unsigned g_bars[GRID_B * 32];

// ---- packed f32x2 helpers ----
__device__ __forceinline__ ull pk2(float lo, float hi) {
    ull r; asm("mov.b64 %0, {%1,%2};" : "=l"(r) : "f"(lo), "f"(hi)); return r;
}
__device__ __forceinline__ float2 upk2(ull v) {
    float2 r; asm("mov.b64 {%0,%1}, %2;" : "=f"(r.x), "=f"(r.y) : "l"(v)); return r;
}
__device__ __forceinline__ ull fma2(ull a, ull b, ull c) {
    ull d; asm("fma.rn.f32x2 %0, %1, %2, %3;" : "=l"(d) : "l"(a), "l"(b), "l"(c)); return d;
}

// ---- per-group grid barrier ----
__device__ __forceinline__ void bar_wait(unsigned* bar, unsigned target) {
    if (threadIdx.x == 0) {
        unsigned v;
        do {
            asm volatile("ld.acquire.gpu.global.u32 %0, [%1];"
                         : "=r"(v) : "l"(bar) : "memory");
        } while (v < target);
    }
    __syncthreads();
}
__device__ __forceinline__ void bar_arrive(unsigned* bar, unsigned total) {
    __syncthreads();                       // all CTA threads' h stores done
    if (threadIdx.x == 0) {
        unsigned old;
        asm volatile("atom.release.gpu.global.add.u32 %0, [%1], %2;"
                     : "=r"(old) : "l"(bar), "r"(1u) : "memory");
        if (old == total - 1u)             // last arrival of this launch: reset
            asm volatile("st.relaxed.gpu.global.u32 [%0], %1;"
                         :: "l"(bar), "r"(0u) : "memory");
    }
}

// ============================================================================
// Kernel A: xp[t][b][:] = x[b][t][:] @ Whx + bh.  8 rows (same b) per CTA.
// ============================================================================
__global__ void __launch_bounds__(128) xproj_kernel(
    const float* __restrict__ x, const float* __restrict__ Whx,
    const float* __restrict__ bh)
{
    __shared__ float xs[8][IDIM];
    int row0 = blockIdx.x * 8;       // row = b*TSEQ + t; 8 consecutive t, same b
    int b = row0 >> 9, t0 = row0 & (TSEQ - 1);
    int tid = threadIdx.x;
    for (int i = tid; i < 8 * IDIM; i += 128)
        xs[i >> 6][i & 63] = x[(size_t)(row0 + (i >> 6)) * IDIM + (i & 63)];
    __syncthreads();

    int j0 = tid * 4;
    ull a[8][2] = {};
    #pragma unroll 4
    for (int k = 0; k < IDIM; k++) {
        float4 w = *reinterpret_cast<const float4*>(Whx + (size_t)k * HDIM + j0);
        ull w01 = pk2(w.x, w.y), w23 = pk2(w.z, w.w);
        #pragma unroll
        for (int r = 0; r < 8; r++) {
            float xv = xs[r][k];
            ull x2 = pk2(xv, xv);
            a[r][0] = fma2(w01, x2, a[r][0]);
            a[r][1] = fma2(w23, x2, a[r][1]);
        }
    }
    float4 bv = *reinterpret_cast<const float4*>(bh + j0);
    #pragma unroll
    for (int r = 0; r < 8; r++) {
        float2 p0 = upk2(a[r][0]), p1 = upk2(a[r][1]);
        float4 o;
        o.x = p0.x + bv.x; o.y = p0.y + bv.y;
        o.z = p1.x + bv.z; o.w = p1.y + bv.w;
        *reinterpret_cast<float4*>(
            g_xp + ((size_t)(t0 + r) * BATCH + b) * HDIM + j0) = o;
    }
}

// ============================================================================
// Kernel B: persistent recurrence. Grid (16 j, 8 b) = 128 CTAs, 128 threads.
// CTA tile 32j x 32b. Whh slice pre-splatted in SMEM ({w,w} pairs, 128 KB).
// h plain-float transposed, staged per step via double-buffered cp.async.cg.
// Warp 2x2 tile over (j,b): warp = (wj, wb), 16j x 16b per warp.
// Thread: 4j x 2b; accumulators pack b-pairs {acc_b0, acc_b1}.
// Per kl per thread: 2 LDS.128 (w-splats) + 1 LDS.64 (h-pair) + 4 FFMA2.
// Barrier is per batch-group (16 CTAs), one padded counter per group.
// ============================================================================
__global__ void __launch_bounds__(STEP_THREADS, 1) rnn_persistent(
    const float* __restrict__ Whh)
{
    extern __shared__ char smraw[];
    float* ws2 = reinterpret_cast<float*>(smraw);   // [512][64] splat pairs, 128 KB
    char*  hsb = smraw + 131072;                    // 2 x [128 k][32 b] floats, 16 KB each

    const int tid  = threadIdx.x;
    const int lane = tid & 31, wrp = tid >> 5;
    const int wj = wrp & 1, wb = wrp >> 1;
    const int jg = lane & 3, bg = lane >> 2;        // 4 j-quads, 8 b-pairs
    const int j0c = blockIdx.x * 32;
    const int b0c = blockIdx.y * 32;
    const int jl0 = wj * 16 + jg * 4;               // local j (quad base)
    const int bl0 = wb * 16 + bg * 2;               // local b (pair base, even)
    const int j0 = j0c + jl0;
    const int b0 = b0c + bl0;
    unsigned* bar = &g_bars[blockIdx.y * 32];

    // ---- build splatted Whh slice in SMEM (once) ----
    for (int i = tid; i < 512 * 32; i += STEP_THREADS) {
        int k = i >> 5, jl = i & 31;
        float w = Whh[(size_t)k * HDIM + j0c + jl];
        *reinterpret_cast<float2*>(ws2 + (size_t)k * 64 + jl * 2) = make_float2(w, w);
    }
    __syncthreads();

    // staging mapping: chunk = 128 k-rows x 32 b floats (128 B/row), 16 KB.
    // 8 segs of 16 B per row; tid -> seg (0..7), krow0 (0..15); 8 passes stride 16.
    const int seg   = tid & 7;
    const int krow0 = tid >> 3;

    for (int t = 0; t < TSEQ; t++) {
        const float* xpt = g_xp + (size_t)t * BATCH * HDIM;
        float4 xv0 = *reinterpret_cast<const float4*>(xpt + (size_t)b0 * HDIM + j0);
        float4 xv1 = *reinterpret_cast<const float4*>(xpt + (size_t)(b0 + 1) * HDIM + j0);
        ull a0 = 0ull, a1 = 0ull, a2 = 0ull, a3 = 0ull;   // {b0,b1} per j of quad

        if (t > 0) {
            bar_wait(bar, (unsigned)t * GRID_J);
            const float* hin = g_ht[(t - 1) & 1];

            // issue chunk 0
            {
                const float* src = hin + (size_t)krow0 * BATCH + b0c + seg * 4;
                uint32_t dst = (uint32_t)__cvta_generic_to_shared(
                    hsb + (size_t)krow0 * 128 + seg * 16);
                #pragma unroll
                for (int p = 0; p < 8; p++)
                    asm volatile("cp.async.cg.shared.global [%0], [%1], 16;"
                                 :: "r"(dst + p * 2048),
                                    "l"(src + (size_t)p * 16 * BATCH) : "memory");
                asm volatile("cp.async.commit_group;" ::: "memory");
            }

            #pragma unroll
            for (int c = 0; c < 4; c++) {
                asm volatile("cp.async.wait_group 0;" ::: "memory");
                __syncthreads();
                if (c < 3) {
                    const float* src = hin + (size_t)((c + 1) * 128 + krow0) * BATCH
                                       + b0c + seg * 4;
                    uint32_t dst = (uint32_t)__cvta_generic_to_shared(
                        hsb + ((size_t)((c + 1) & 1)) * 16384
                            + (size_t)krow0 * 128 + seg * 16);
                    #pragma unroll
                    for (int p = 0; p < 8; p++)
                        asm volatile("cp.async.cg.shared.global [%0], [%1], 16;"
                                     :: "r"(dst + p * 2048),
                                        "l"(src + (size_t)p * 16 * BATCH) : "memory");
                    asm volatile("cp.async.commit_group;" ::: "memory");
                }
                // compute chunk c from buffer c&1
                const float* wk = ws2 + (size_t)(c * 128) * 64 + jl0 * 2;
                const char*  hk = hsb + (c & 1) * 16384 + bl0 * 4;
                #pragma unroll 8
                for (int kl = 0; kl < 128; kl++) {
                    ulonglong2 wA = *reinterpret_cast<const ulonglong2*>(wk + (size_t)kl * 64);
                    ulonglong2 wB = *reinterpret_cast<const ulonglong2*>(wk + (size_t)kl * 64 + 4);
                    ull hb = *reinterpret_cast<const ull*>(hk + (size_t)kl * 128);
                    a0 = fma2(wA.x, hb, a0);
                    a1 = fma2(wA.y, hb, a1);
                    a2 = fma2(wB.x, hb, a2);
                    a3 = fma2(wB.y, hb, a3);
                }
            }
        }

        // ---- epilogue: add xp, tanh, store plain transposed h ----
        float* hout = g_ht[t & 1];
        float2 p0 = upk2(a0), p1 = upk2(a1), p2 = upk2(a2), p3 = upk2(a3);
        float2 o0 = make_float2(tanhf(xv0.x + p0.x), tanhf(xv1.x + p0.y));
        float2 o1 = make_float2(tanhf(xv0.y + p1.x), tanhf(xv1.y + p1.y));
        float2 o2 = make_float2(tanhf(xv0.z + p2.x), tanhf(xv1.z + p2.y));
        float2 o3 = make_float2(tanhf(xv0.w + p3.x), tanhf(xv1.w + p3.y));
        *reinterpret_cast<float2*>(hout + (size_t)(j0 + 0) * BATCH + b0) = o0;
        *reinterpret_cast<float2*>(hout + (size_t)(j0 + 1) * BATCH + b0) = o1;
        *reinterpret_cast<float2*>(hout + (size_t)(j0 + 2) * BATCH + b0) = o2;
        *reinterpret_cast<float2*>(hout + (size_t)(j0 + 3) * BATCH + b0) = o3;

        bar_arrive(bar, (unsigned)TSEQ * GRID_J);
    }
}

// ============================================================================
// Kernel C: out[b][:] = softmax(h_last[b][:] @ Wph + bo). h_last = g_ht[1]
// (t=511 -> buffer 1), transposed: element [k][b] at k*BATCH + b.
// ============================================================================
__global__ void __launch_bounds__(128) out_softmax_kernel(
    const float* __restrict__ Wph, const float* __restrict__ bo,
    float* __restrict__ out)
{
    __shared__ float hsr[HDIM];
    __shared__ float red[128];
    int b = blockIdx.x, tid = threadIdx.x;
    for (int k = tid; k < HDIM; k += 128)
        hsr[k] = g_ht[1][(size_t)k * BATCH + b];
    __syncthreads();

    int j0 = tid * 4;
    ull a0 = 0ull, a1 = 0ull;
    #pragma unroll 8
    for (int k = 0; k < HDIM; k++) {
        float4 w = *reinterpret_cast<const float4*>(Wph + (size_t)k * ODIM + j0);
        ull hv = pk2(hsr[k], hsr[k]);
        a0 = fma2(pk2(w.x, w.y), hv, a0);
        a1 = fma2(pk2(w.z, w.w), hv, a1);
    }
    float4 bv = *reinterpret_cast<const float4*>(bo + j0);
    float2 p0 = upk2(a0), p1 = upk2(a1);
    float4 v;
    v.x = p0.x + bv.x; v.y = p0.y + bv.y;
    v.z = p1.x + bv.z; v.w = p1.y + bv.w;

    float m = fmaxf(fmaxf(v.x, v.y), fmaxf(v.z, v.w));
    red[tid] = m;
    __syncthreads();
    for (int s = 64; s > 0; s >>= 1) {
        if (tid < s) red[tid] = fmaxf(red[tid], red[tid + s]);
        __syncthreads();
    }
    m = red[0];
    __syncthreads();

    v.x = expf(v.x - m); v.y = expf(v.y - m);
    v.z = expf(v.z - m); v.w = expf(v.w - m);
    red[tid] = v.x + v.y + v.z + v.w;
    __syncthreads();
    for (int s = 64; s > 0; s >>= 1) {
        if (tid < s) red[tid] += red[tid + s];
        __syncthreads();
    }
    float inv = 1.0f / red[0];
    v.x *= inv; v.y *= inv; v.z *= inv; v.w *= inv;
    *reinterpret_cast<float4*>(out + (size_t)b * ODIM + j0) = v;
}

// ============================================================================
extern "C" void kernel_launch(void* const* d_in, const int* in_sizes, int n_in,
                              void* d_out, int out_size)
{
    const float* x   = (const float*)d_in[0];
    const float* Whx = (const float*)d_in[1];
    const float* Whh = (const float*)d_in[2];
    const float* bh  = (const float*)d_in[3];
    const float* Wph = (const float*)d_in[4];
    const float* bo  = (const float*)d_in[5];
    float* out = (float*)d_out;

    cudaFuncSetAttribute(rnn_persistent,
                         cudaFuncAttributeMaxDynamicSharedMemorySize, 163840);

    xproj_kernel<<<BATCH * TSEQ / 8, 128>>>(x, Whx, bh);
    rnn_persistent<<<dim3(GRID_J, GRID_B), STEP_THREADS, 163840>>>(Whh);
    out_softmax_kernel<<<BATCH, 128>>>(Wph, bo, out);
}